// round 14
// baseline (speedup 1.0000x reference)
#include <cuda_runtime.h>
#include <math.h>

// ARIMA sliding-window loss, collapsed to:
//   err[t] = y[t+33] - K1*FIR(g, win) + M1q*sum - K2q*sqrt(32*sq - sum^2 + 1024*eps)
//   loss   = (sum(y[:33]^2) + sum(err^2)) / S
// Double-tile cp.async pipeline: each CTA stages TWO 1024-t tiles up front
// (LDGSTS, one commit group per tile); tile-1 DRAM latency hides behind tile-0
// compute. 512 CTAs, __launch_bounds__(128,4) -> 128-reg budget: fully
// register-resident 44-float window, single-phase 32-tap FIR, RPT=8.
// R13 bug fixed: __syncthreads() before reading sc[] (constants race).

#define PW     32
#define T0     33
#define EPSF   1e-5f
#define TPB    128
#define RPT    8
#define TILE   (TPB * RPT)       // 1024 t per tile
#define TILES  2
#define CTAT   (TILE * TILES)    // 2048 t per CTA
#define NCHUNK 267               // 16B chunks per tile: floats [0, 1068)
#define BSTRIDE 1072             // floats per buffer (padded)
#define MAXB   1024

__device__ float        g_part[MAXB];
__device__ unsigned int g_ctr = 0;   // atomicInc wraps to 0 each launch

__device__ __forceinline__ float sqrt_apx(float x) {
    float r; asm("sqrt.approx.f32 %0, %1;" : "=f"(r) : "f"(x)); return r;
}
__device__ __forceinline__ void cp16(float* dst, const float* src) {
    unsigned int d = (unsigned int)__cvta_generic_to_shared(dst);
    asm volatile("cp.async.ca.shared.global [%0], [%1], 16;" :: "r"(d), "l"(src));
}

__global__ void __launch_bounds__(TPB, 4) arima_fused(
    const float* __restrict__ y,
    const float* __restrict__ w,
    const float* __restrict__ ab,
    const float* __restrict__ rw_,
    const float* __restrict__ rb_,
    float* __restrict__ out,
    int T, int S)
{
    __shared__ __align__(16) float sy[TILES][BSTRIDE];
    __shared__ __align__(16) float sg[PW];
    __shared__ float  sc[3];
    __shared__ double sred[TPB / 32];
    __shared__ int    isLast;

    const float4* sg4 = (const float4*)sg;
    const int tid = threadIdx.x;
    const int bid = blockIdx.x;
    const int tb  = bid * CTAT;

    // FIR taps from ar_weight + differencing structure
    if (tid < PW) {
        float wj  = w[tid];
        float wj1 = (tid < PW - 1) ? w[tid + 1] : 0.0f;
        float gv  = wj - wj1;
        if (tid == PW - 2) gv -= 1.0f;   // g[30] = w30 - w31 - 1
        if (tid == PW - 1) gv += 1.0f;   // g[31] = w31 + 1
        sg[tid] = gv;
    }
    if (tid == 0) {
        float rw = rw_[0], rb = rb_[0], b = ab[0], w0 = w[0];
        float denom = rw + EPSF * EPSF;
        float K1 = rw / denom;
        float K2 = (w0 * rb - rb + b) / denom;
        float M1 = fmaf(K1, w0, -1.0f);
        sc[0] = K1;
        sc[1] = K2 * (1.0f / 32.0f);      // K2q
        sc[2] = M1 * (1.0f / 32.0f);      // M1q
    }

    // Stage BOTH tiles up front via cp.async; one commit group per tile.
    #pragma unroll
    for (int tt = 0; tt < TILES; tt++) {
        const int base = tb + tt * TILE;
        #pragma unroll
        for (int c = 0; c < 3; c++) {
            int i = tid + c * TPB;                 // 16B chunk index
            if (i < NCHUNK) {
                int gf = base + 4 * i;
                if (gf + 4 <= S) {
                    cp16(&sy[tt][4 * i], y + gf);
                } else {                           // boundary: guarded scalar fill
                    float4 v;
                    v.x = (gf     < S) ? y[gf]     : 0.f;
                    v.y = (gf + 1 < S) ? y[gf + 1] : 0.f;
                    v.z = (gf + 2 < S) ? y[gf + 2] : 0.f;
                    v.w = (gf + 3 < S) ? y[gf + 3] : 0.f;
                    *(float4*)&sy[tt][4 * i] = v;
                }
            }
        }
        asm volatile("cp.async.commit_group;" ::: "memory");
    }

    // Order sc[]/sg[] writes before any thread reads them. This barrier does
    // NOT wait for the async copies (wait_group below does), so tile-1 staging
    // still overlaps tile-0 compute.
    __syncthreads();

    const float K1 = sc[0], K2q = sc[1], M1q = sc[2];
    const float C0 = 1024.0f * EPSF;

    float esum_f = 0.0f;

    #pragma unroll
    for (int tt = 0; tt < TILES; tt++) {
        if (tt == 0) asm volatile("cp.async.wait_group 1;" ::: "memory");
        else         asm volatile("cp.async.wait_group 0;" ::: "memory");
        __syncthreads();

        const float4* sy4 = (const float4*)sy[tt];
        const int t0 = tb + tt * TILE + tid * RPT;   // xv[m] = y[t0+m]

        // Full 44-float window in registers: 11 aligned LDS.128
        float xv[44];
        #pragma unroll
        for (int c = 0; c < 11; c++) {
            float4 v = sy4[2 * tid + c];
            xv[4*c + 0] = v.x; xv[4*c + 1] = v.y;
            xv[4*c + 2] = v.z; xv[4*c + 3] = v.w;
        }

        // 8 FIR chains + sum/sumsq over xv[1..32]
        float f[RPT];
        #pragma unroll
        for (int r = 0; r < RPT; r++) f[r] = 0.0f;
        float sum = 0.f, sq = 0.f;
        #pragma unroll
        for (int c = 0; c < 8; c++) {
            float4 gc = sg4[c];
            const float ge[4] = {gc.x, gc.y, gc.z, gc.w};
            #pragma unroll
            for (int e = 0; e < 4; e++) {
                const int j = 4 * c + e;
                float xj = xv[1 + j];
                sum += xj;
                sq   = fmaf(xj, xj, sq);
                #pragma unroll
                for (int r = 0; r < RPT; r++)
                    f[r] = fmaf(ge[e], xv[1 + j + r], f[r]);
            }
        }

        // Epilogue: single path, tail masked by predicated accumulate
        #pragma unroll
        for (int r = 0; r < RPT; r++) {
            if (r > 0) {
                float xn = xv[32 + r], xo = xv[r];
                sum += xn - xo;
                sq   = fmaf(xn, xn, sq);
                sq   = fmaf(-xo, xo, sq);
            }
            float u   = fmaf(-sum, sum, fmaf(32.0f, sq, C0));
            float sd  = sqrt_apx(u);
            float err = fmaf(-K2q, sd, fmaf(M1q, sum, fmaf(-K1, f[r], xv[33 + r])));
            if (t0 + r < T)
                esum_f = fmaf(err, err, esum_f);
        }
    }

    // Block reduction (double from warp level up)
    double esum = (double)esum_f;
    #pragma unroll
    for (int o = 16; o > 0; o >>= 1)
        esum += __shfl_down_sync(0xffffffffu, esum, o);
    if ((tid & 31) == 0) sred[tid >> 5] = esum;
    __syncthreads();
    if (tid == 0) {
        double bs = 0.0;
        #pragma unroll
        for (int i = 0; i < TPB / 32; i++) bs += sred[i];
        g_part[bid] = (float)bs;
        __threadfence();
        unsigned pos = atomicInc(&g_ctr, gridDim.x - 1);
        isLast = (pos == gridDim.x - 1);
    }
    __syncthreads();

    // Last block: deterministic final reduction + head term
    if (isLast) {
        __threadfence();
        double s = 0.0;
        for (int i = tid; i < (int)gridDim.x; i += TPB) s += (double)g_part[i];
        for (int i = tid; i < T0; i += TPB) { double v = (double)y[i]; s += v * v; }
        #pragma unroll
        for (int o = 16; o > 0; o >>= 1)
            s += __shfl_down_sync(0xffffffffu, s, o);
        if ((tid & 31) == 0) sred[tid >> 5] = s;
        __syncthreads();
        if (tid == 0) {
            double tot = 0.0;
            #pragma unroll
            for (int i = 0; i < TPB / 32; i++) tot += sred[i];
            out[0] = (float)(tot / (double)S);
        }
    }
}

extern "C" void kernel_launch(void* const* d_in, const int* in_sizes, int n_in,
                              void* d_out, int out_size)
{
    const float* y  = (const float*)d_in[0];
    const float* w  = (const float*)d_in[1];
    const float* ab = (const float*)d_in[2];
    const float* rw = (const float*)d_in[3];
    const float* rb = (const float*)d_in[4];
    int S = in_sizes[0];
    int T = S - T0;
    int nblocks = (T + CTAT - 1) / CTAT;   // S=1M -> 512 CTAs (single wave @4/SM)
    if (nblocks > MAXB) nblocks = MAXB;
    arima_fused<<<nblocks, TPB>>>(y, w, ab, rw, rb, (float*)d_out, T, S);
}